// round 11
// baseline (speedup 1.0000x reference)
#include <cuda_runtime.h>
#include <math.h>

// HorizonReward — 2-warp warp-specialized UT cartpole rollout.
// Single-warp versions are pinned at ~650 cyc/step by in-order issue
// (~400 cyc fma-pipe) + exposed latency (~250 cyc). Split across two
// warps (two SMSPs): W0 = moments/covariance/Cholesky/prep, W1 = redundant
// dynamics + policy. One __syncthreads per step; double-buffered smem
// handoff (u: W1->W0, prep pack: W0->W1). Numeric scheme = verified R10.

typedef unsigned long long u64;

__device__ __forceinline__ u64 pk(float lo, float hi) {
    u64 r; asm("mov.b64 %0,{%1,%2};" : "=l"(r) : "f"(lo), "f"(hi)); return r;
}
__device__ __forceinline__ void upk(u64 a, float& x, float& y) {
    asm("mov.b64 {%0,%1},%2;" : "=f"(x), "=f"(y) : "l"(a));
}
__device__ __forceinline__ u64 sp2(float s) { return pk(s, s); }
__device__ __forceinline__ u64 fma2_(u64 a, u64 b, u64 c) {
    u64 d; asm("fma.rn.f32x2 %0,%1,%2,%3;" : "=l"(d) : "l"(a), "l"(b), "l"(c)); return d;
}
__device__ __forceinline__ u64 mul2_(u64 a, u64 b) {
    u64 d; asm("mul.rn.f32x2 %0,%1,%2;" : "=l"(d) : "l"(a), "l"(b)); return d;
}
__device__ __forceinline__ u64 add2_(u64 a, u64 b) {
    u64 d; asm("add.rn.f32x2 %0,%1,%2;" : "=l"(d) : "l"(a), "l"(b)); return d;
}
__device__ __forceinline__ float rcp_(float x) {
    float r; asm("rcp.approx.f32 %0,%1;" : "=f"(r) : "f"(x)); return r;
}
__device__ __forceinline__ float ex2_(float x) {
    float r; asm("ex2.approx.f32 %0,%1;" : "=f"(r) : "f"(x)); return r;
}
// radix-4 two-stage 16-lane reduction (parallel shfls within each stage)
__device__ __forceinline__ float red16_r4(float x) {
    const float a = __shfl_xor_sync(0xffffffffu, x, 4);
    const float b = __shfl_xor_sync(0xffffffffu, x, 8);
    const float c = __shfl_xor_sync(0xffffffffu, x, 12);
    x = (x + a) + (b + c);
    const float d = __shfl_xor_sync(0xffffffffu, x, 1);
    const float e = __shfl_xor_sync(0xffffffffu, x, 2);
    const float f = __shfl_xor_sync(0xffffffffu, x, 3);
    return (x + d) + (e + f);
}

#define DTc      0.05f
#define K1c      (0.05f / 1.1f)
#define K3c      (0.5f * (4.0f / 3.0f))
#define K2c      (0.5f * 0.1f / 1.1f)
#define INV11c   (1.0f / 1.1f)
#define DIAG5c   (5.0f * (0.01f * 0.05f + 2.0f * 1e-6f))

__global__ __launch_bounds__(64, 1)
void horizon_reward_kernel(const float* __restrict__ p, float* __restrict__ out)
{
    const int tid = threadIdx.x;
    const int wid = tid >> 5;
    const int lane = tid & 31;
    const int jj = lane & 15;

    __shared__ float sm_u[2];
    __shared__ float sm_prep[2][9][6];   // [buf][pt][tks,g98,c,rd,r1,r3]

    // ---- sigma-point roles (used by both warps) ----
    const int pt = jj;
    const int col = (pt == 0) ? 3 : ((pt - 1) & 3);
    const float sgn = (pt >= 1 && pt <= 4) ? 1.f : ((pt >= 5 && pt <= 8) ? -1.f : 0.f);
    const bool isC0 = (col == 0), isC1 = (col == 1), isC2 = (col == 2);
    const int pp = (pt <= 8) ? pt : 0;

    const u64 NL2E2 = sp2(-1.4426950408889634f);
    const u64 NM1_2 = sp2(-1.f);
    const u64 W0_2 = sp2(0.2f), WI_2 = sp2(0.1f), HALF2 = sp2(0.5f);

    // ---- state (both warps track m; W0 owns S) ----
    float m0 = 0.f, m1 = 0.f, m2 = 0.1f, m3 = 0.f;
    const float r0i = 2.23606797749979f * 1e-3f;
    float S00 = r0i, S10 = 0.f, S20 = 0.f, S30 = 0.f;
    float S11 = r0i, S21 = 0.f, S31 = 0.f;
    float S22 = r0i, S32 = 0.f;
    float S33 = r0i;

    // ---- per-warp persistent registers ----
    float tks_, g98_, c_, rd_, r1_, r3_;     // dynamics prep (both warps)
    float u_reg = 0.f;                       // W1: current u
    float reward = 0.f;                      // W0

    // W1 policy params (loaded only in warp 1; harmless in W0)
    u64 nmuA[4], LA[10], nmuB[4], LB[10];
    float wA0 = 0.f, wA1 = 0.f, wB0 = 0.f, wB1 = 0.f;
    if (wid == 1) {
        const int a0 = jj, a1 = jj + 16, b0 = jj + 32, b1 = jj + 48;
        const bool hb1 = (b1 < 50);
        wA0 = p[a0]; wA1 = p[a1];
        wB0 = p[b0]; wB1 = hb1 ? p[b1] : 0.f;
        #pragma unroll
        for (int k = 0; k < 4; ++k) {
            nmuA[k] = pk(-p[50 + k * 50 + a0], -p[50 + k * 50 + a1]);
            nmuB[k] = pk(-p[50 + k * 50 + b0], hb1 ? -p[50 + k * 50 + b1] : 0.f);
        }
        #pragma unroll
        for (int t = 0; t < 10; ++t) {
            LA[t] = pk(p[250 + a0 * 10 + t], p[250 + a1 * 10 + t]);
            LB[t] = pk(p[250 + b0 * 10 + t], hb1 ? p[250 + b1 * 10 + t] : 0.f);
        }
    }

    // ---- initial prep (both warps compute locally from S_0) ----
    {
        r1_ = sgn * (isC0 ? S10 : (isC1 ? S11 : 0.f));
        const float r2 = sgn * (isC0 ? S20 : (isC1 ? S21 : (isC2 ? S22 : 0.f)));
        r3_ = sgn * (isC0 ? S30 : (isC1 ? S31 : (isC2 ? S32 : S33)));
        const float th = m2 + r2, thd = m3 + r3_;
        const float s = __sinf(th);
        c_ = __cosf(th);
        rd_ = rcp_(fmaf(-K2c * c_, c_, K3c));
        tks_ = ((thd * thd) * K1c) * s;
        g98_ = 9.8f * s;
    }

    // ---- W1: initial u = policy(m_init) -> sm_u[0] ----
    if (wid == 1) {
        u64 d0 = add2_(sp2(m0), nmuA[0]), d1 = add2_(sp2(m1), nmuA[1]);
        u64 d2 = add2_(sp2(m2), nmuA[2]), d3 = add2_(sp2(m3), nmuA[3]);
        u64 l0 = mul2_(LA[0], d0);
        l0 = fma2_(LA[4], d1, l0); l0 = fma2_(LA[5], d2, l0); l0 = fma2_(LA[7], d3, l0);
        u64 l1 = mul2_(LA[1], d1); l1 = fma2_(LA[6], d2, l1); l1 = fma2_(LA[8], d3, l1);
        u64 l2 = mul2_(LA[2], d2); l2 = fma2_(LA[9], d3, l2);
        u64 l3 = mul2_(LA[3], d3);
        u64 qA = fma2_(l1, l1, mul2_(l0, l0));
        qA = add2_(qA, fma2_(l3, l3, mul2_(l2, l2)));
        qA = mul2_(qA, NL2E2);
        d0 = add2_(sp2(m0), nmuB[0]); d1 = add2_(sp2(m1), nmuB[1]);
        d2 = add2_(sp2(m2), nmuB[2]); d3 = add2_(sp2(m3), nmuB[3]);
        l0 = mul2_(LB[0], d0);
        l0 = fma2_(LB[4], d1, l0); l0 = fma2_(LB[5], d2, l0); l0 = fma2_(LB[7], d3, l0);
        l1 = mul2_(LB[1], d1); l1 = fma2_(LB[6], d2, l1); l1 = fma2_(LB[8], d3, l1);
        l2 = mul2_(LB[2], d2); l2 = fma2_(LB[9], d3, l2);
        l3 = mul2_(LB[3], d3);
        u64 qB = fma2_(l1, l1, mul2_(l0, l0));
        qB = add2_(qB, fma2_(l3, l3, mul2_(l2, l2)));
        qB = mul2_(qB, NL2E2);
        float qa0, qa1, qb0, qb1;
        upk(qA, qa0, qa1); upk(qB, qb0, qb1);
        float acc = fmaf(wA0, ex2_(qa0), wA1 * ex2_(qa1))
                  + fmaf(wB0, ex2_(qb0), wB1 * ex2_(qb1));
        acc = red16_r4(acc);
        u_reg = fminf(fmaxf(acc, -10.f), 10.f);
        if (lane == 0) sm_u[0] = u_reg;
    }
    __syncthreads();

    #pragma unroll 1
    for (int t = 0; t < 60; ++t) {
        const int cb = t & 1;            // buffer carrying u_t / prep_t inputs
        const int nb = 1 - cb;           // buffer written this body

        if (wid == 0) {
            // =============== W0: state warp ===============
            const float u = sm_u[cb];
            const float ud = u * INV11c;
            const float temp = tks_ + ud;
            const float num = fmaf(-c_, temp, g98_);
            const float ta = num * rd_;
            const float xa = fmaf(-K1c, ta * c_, temp);
            const float y1 = fmaf(DTc, xa, r1_);
            const float y3 = fmaf(DTc, ta, r3_);

            // gather all 9 (y1,y3): parallel shfl.idx
            u64 z[9];
            #pragma unroll
            for (int j = 0; j < 9; ++j) {
                const float g1 = __shfl_sync(0xffffffffu, y1, j);
                const float g3 = __shfl_sync(0xffffffffu, y3, j);
                z[j] = pk(g1, g3);
            }
            // packed means
            const u64 sA = add2_(add2_(z[1], z[2]), add2_(z[3], z[4]));
            const u64 sB = add2_(add2_(z[5], z[6]), add2_(z[7], z[8]));
            const u64 d13 = fma2_(WI_2, add2_(sA, sB), mul2_(W0_2, z[0]));
            float d1, d3; upk(d13, d1, d3);

            // linear-coordinate covariance entries (old S)
            const float A0 = fmaf(DTc, S10, S00);
            const float A1v = DTc * S11;
            const float C0 = fmaf(DTc, S30, S20);
            const float C1 = fmaf(DTc, S31, S21);
            const float C2v = fmaf(DTc, S32, S22);
            const float C3 = DTc * S33;
            const float c00 = fmaf(A1v, A1v, A0 * A0) + DIAG5c;
            const float c20 = fmaf(A1v, C1, A0 * C0);
            const float c22 = fmaf(C3, C3, fmaf(C2v, C2v, fmaf(C1, C1, C0 * C0))) + DIAG5c;
            const u64 A0h2 = sp2(0.5f * A0), A1h2 = sp2(0.5f * A1v);
            const u64 C0h2 = sp2(0.5f * C0), C1h2 = sp2(0.5f * C1);
            const u64 C2h2 = sp2(0.5f * C2v), C3h2 = sp2(0.5f * C3);

            // moments from gathered z
            const u64 gz1 = fma2_(z[5], NM1_2, z[1]);
            const u64 gz2 = fma2_(z[6], NM1_2, z[2]);
            const u64 gz3 = fma2_(z[7], NM1_2, z[3]);
            const u64 gz4 = fma2_(z[8], NM1_2, z[4]);
            const u64 p1030 = fma2_(A1h2, gz2, mul2_(A0h2, gz1));
            u64 p2132 = fma2_(C1h2, gz2, mul2_(C0h2, gz1));
            p2132 = fma2_(C2h2, gz3, p2132);
            p2132 = fma2_(C3h2, gz4, p2132);
            float p10, p30, p21, p32;
            upk(p1030, p10, p30); upk(p2132, p21, p32);
            u64 sq = mul2_(z[1], z[1]);
            sq = fma2_(z[2], z[2], sq); sq = fma2_(z[3], z[3], sq);
            sq = fma2_(z[4], z[4], sq); sq = fma2_(z[5], z[5], sq);
            sq = fma2_(z[6], z[6], sq); sq = fma2_(z[7], z[7], sq);
            sq = fma2_(z[8], z[8], sq);
            const u64 p1133 = fma2_(HALF2, sq, mul2_(z[0], z[0]));
            float p11, p33; upk(p1133, p11, p33);
            float y1j[9], y3j[9];
            #pragma unroll
            for (int j = 0; j < 9; ++j) upk(z[j], y1j[j], y3j[j]);
            float xs = y1j[1] * y3j[1];
            xs = fmaf(y1j[2], y3j[2], xs); xs = fmaf(y1j[3], y3j[3], xs);
            xs = fmaf(y1j[4], y3j[4], xs); xs = fmaf(y1j[5], y3j[5], xs);
            xs = fmaf(y1j[6], y3j[6], xs); xs = fmaf(y1j[7], y3j[7], xs);
            xs = fmaf(y1j[8], y3j[8], xs);
            const float p13 = fmaf(0.5f, xs, y1j[0] * y3j[0]);

            // de-meaned covariance + next mean
            const float n0 = fmaf(DTc, m1, m0);
            const float n2 = fmaf(DTc, m3, m2);
            const float n1 = m1 + d1;
            const float n3 = m3 + d3;
            const float f1 = 5.f * d1, f3 = 5.f * d3;
            const float c11 = fmaf(-f1, d1, p11) + DIAG5c;
            const float c31 = fmaf(-f1, d3, p13);
            const float c33 = fmaf(-f3, d3, p33) + DIAG5c;
            const float c10 = p10, c30 = p30, c21 = p21, c32 = p32;

            // reward
            const float q = fmaf(n0, n0, fmaf(n1, n1, fmaf(10.f * n2, n2, n3 * n3)));
            const float tr = c00 + c11 + fmaf(10.f, c22, c33);
            reward -= fmaf(0.2f, tr, q);

            // Cholesky -> S_{t+1}
            const float rr0 = rsqrtf(c00);
            S00 = c00 * rr0;
            S10 = c10 * rr0; S20 = c20 * rr0; S30 = c30 * rr0;
            const float a11 = fmaf(-S10, S10, c11);
            const float rr1 = rsqrtf(a11);
            S11 = a11 * rr1;
            S21 = fmaf(-S20, S10, c21) * rr1;
            S31 = fmaf(-S30, S10, c31) * rr1;
            const float a22 = fmaf(-S21, S21, fmaf(-S20, S20, c22));
            const float rr2 = rsqrtf(a22);
            S22 = a22 * rr2;
            S32 = fmaf(-S31, S21, fmaf(-S30, S20, c32)) * rr2;
            const float a33 = fmaf(-S32, S32, fmaf(-S31, S31, fmaf(-S30, S30, c33)));
            S33 = a33 * rsqrtf(a33);

            // prep for step t+1 (own regs + pack for W1)
            m0 = n0; m1 = n1; m2 = n2; m3 = n3;
            r1_ = sgn * (isC0 ? S10 : (isC1 ? S11 : 0.f));
            const float r2n = sgn * (isC0 ? S20 : (isC1 ? S21 : (isC2 ? S22 : 0.f)));
            r3_ = sgn * (isC0 ? S30 : (isC1 ? S31 : (isC2 ? S32 : S33)));
            const float thn = m2 + r2n, thdn = m3 + r3_;
            const float sn = __sinf(thn);
            c_ = __cosf(thn);
            rd_ = rcp_(fmaf(-K2c * c_, c_, K3c));
            tks_ = ((thdn * thdn) * K1c) * sn;
            g98_ = 9.8f * sn;
            if (lane < 9) {
                sm_prep[nb][pt][0] = tks_;
                sm_prep[nb][pt][1] = g98_;
                sm_prep[nb][pt][2] = c_;
                sm_prep[nb][pt][3] = rd_;
                sm_prep[nb][pt][4] = r1_;
                sm_prep[nb][pt][5] = r3_;
            }
        } else {
            // =============== W1: policy warp ===============
            const float ud = u_reg * INV11c;
            const float temp = tks_ + ud;
            const float num = fmaf(-c_, temp, g98_);
            const float ta = num * rd_;
            const float xa = fmaf(-K1c, ta * c_, temp);
            const float y1 = fmaf(DTc, xa, r1_);
            const float y3 = fmaf(DTc, ta, r3_);

            u64 z[9];
            #pragma unroll
            for (int j = 0; j < 9; ++j) {
                const float g1 = __shfl_sync(0xffffffffu, y1, j);
                const float g3 = __shfl_sync(0xffffffffu, y3, j);
                z[j] = pk(g1, g3);
            }
            const u64 sA = add2_(add2_(z[1], z[2]), add2_(z[3], z[4]));
            const u64 sB = add2_(add2_(z[5], z[6]), add2_(z[7], z[8]));
            const u64 d13 = fma2_(WI_2, add2_(sA, sB), mul2_(W0_2, z[0]));
            float d1, d3; upk(d13, d1, d3);

            const float n0 = fmaf(DTc, m1, m0);
            const float n2 = fmaf(DTc, m3, m2);
            const float n1 = m1 + d1;
            const float n3 = m3 + d3;
            m0 = n0; m1 = n1; m2 = n2; m3 = n3;

            // policy(n)
            u64 d0 = add2_(sp2(n0), nmuA[0]), dd1 = add2_(sp2(n1), nmuA[1]);
            u64 d2 = add2_(sp2(n2), nmuA[2]), dd3 = add2_(sp2(n3), nmuA[3]);
            u64 l0 = mul2_(LA[0], d0);
            l0 = fma2_(LA[4], dd1, l0); l0 = fma2_(LA[5], d2, l0); l0 = fma2_(LA[7], dd3, l0);
            u64 l1 = mul2_(LA[1], dd1); l1 = fma2_(LA[6], d2, l1); l1 = fma2_(LA[8], dd3, l1);
            u64 l2 = mul2_(LA[2], d2); l2 = fma2_(LA[9], dd3, l2);
            u64 l3 = mul2_(LA[3], dd3);
            u64 qA = fma2_(l1, l1, mul2_(l0, l0));
            qA = add2_(qA, fma2_(l3, l3, mul2_(l2, l2)));
            qA = mul2_(qA, NL2E2);
            d0 = add2_(sp2(n0), nmuB[0]); dd1 = add2_(sp2(n1), nmuB[1]);
            d2 = add2_(sp2(n2), nmuB[2]); dd3 = add2_(sp2(n3), nmuB[3]);
            l0 = mul2_(LB[0], d0);
            l0 = fma2_(LB[4], dd1, l0); l0 = fma2_(LB[5], d2, l0); l0 = fma2_(LB[7], dd3, l0);
            l1 = mul2_(LB[1], dd1); l1 = fma2_(LB[6], d2, l1); l1 = fma2_(LB[8], dd3, l1);
            l2 = mul2_(LB[2], d2); l2 = fma2_(LB[9], dd3, l2);
            l3 = mul2_(LB[3], dd3);
            u64 qB = fma2_(l1, l1, mul2_(l0, l0));
            qB = add2_(qB, fma2_(l3, l3, mul2_(l2, l2)));
            qB = mul2_(qB, NL2E2);
            float qa0, qa1, qb0, qb1;
            upk(qA, qa0, qa1); upk(qB, qb0, qb1);
            float acc = fmaf(wA0, ex2_(qa0), wA1 * ex2_(qa1))
                      + fmaf(wB0, ex2_(qb0), wB1 * ex2_(qb1));
            acc = red16_r4(acc);
            u_reg = fminf(fmaxf(acc, -10.f), 10.f);
            if (lane == 0) sm_u[nb] = u_reg;
        }

        __syncthreads();

        if (wid == 1) {
            // load prep for step t+1 (written by W0 into buffer nb)
            tks_ = sm_prep[nb][pp][0];
            g98_ = sm_prep[nb][pp][1];
            c_   = sm_prep[nb][pp][2];
            rd_  = sm_prep[nb][pp][3];
            r1_  = sm_prep[nb][pp][4];
            r3_  = sm_prep[nb][pp][5];
        }
    }

    if (tid == 0) out[0] = reward;
}

extern "C" void kernel_launch(void* const* d_in, const int* in_sizes, int n_in,
                              void* d_out, int out_size) {
    (void)in_sizes; (void)n_in; (void)out_size;
    horizon_reward_kernel<<<1, 64>>>((const float*)d_in[0], (float*)d_out);
}